// round 12
// baseline (speedup 1.0000x reference)
#include <cuda_runtime.h>
#include <math.h>

// pyGAMNet on GB300.
// Cols 0..47: per-feature scalar MLP 1->40->20->1 (ReLU)  == scalar function f_n(x).
// Cols 48..63: class_bias[c, (int)x] gather.
//
// R12: R8's proven gather geometry (16 smem regions per warp x 2 rows, one
// LDS.64 (m,c) + fma per element, branch-free uniform numeric/cat path), but
// regions are feature-DUOS (2 cols, float2 I/O) so a block covers 32 columns:
// table ~100KB -> TWO 1024-thread blocks per SM (64 warps) with unchanged
// conflict profile. Balanced split: A = num 0..23 + cat 0..7, B = rest.

#define BSZ   131072
#define NCOL  64
#define NF    48
#define H0N   40
#define H1N   20

#define NB    512
#define XMIN  (-6.0f)
#define XMAX  (6.0f)
#define WB    (12.0f / 512.0f)        // 3/128, exact in fp32
#define SCALE (512.0f / 12.0f)
#define OFFB  256.0f                  // 6 * 512/12, exact
#define INVW  (512.0f / 12.0f)

#define EVAL_TPB   1024
#define NSLOT      148
#define EVAL_GRID  (2 * NSLOT)        // A: bid<148, B: bid-148 (same SM via LUT)
#define ROWS_PB    ((BSZ + NSLOT - 1) / NSLOT)   // 886

// smem float2 layout: 12 numeric duo-regions of stride 1025 (=2*NB+1, odd ->
// duo bases cover all 16 pair-banks), then 4 cat duo-regions of 65.
#define REG_F2     1025
#define CAT_F2     65
#define CATOFF_F2  (12 * REG_F2)                 // 12300
#define TAB_F2     (CATOFF_F2 + 4 * CAT_F2)      // 12560
#define SMEM_EVAL  (TAB_F2 * 8)                  // 100480 B

__device__ float2 g_tab[NF][NB];      // per bucket: (slope m, intercept c)

// ---------------------------------------------------------------------------
// Exact fallback: full MLP eval for one (feature, x). ~Never executed.
// ---------------------------------------------------------------------------
__device__ __noinline__ float mlp_exact(
    int n, float x,
    const float* __restrict__ W0, const float* __restrict__ b0,
    const float* __restrict__ W1, const float* __restrict__ b1,
    const float* __restrict__ W2, const float* __restrict__ b2)
{
    float acc[H1N];
    for (int k = 0; k < H1N; k++) acc[k] = b1[n * H1N + k];
    for (int j = 0; j < H0N; j++) {
        const float h0 = fmaxf(fmaf(x, W0[n * H0N + j], b0[n * H0N + j]), 0.0f);
        const float* w1r = &W1[(n * H0N + j) * H1N];
        for (int k = 0; k < H1N; k++) acc[k] = fmaf(w1r[k], h0, acc[k]);
    }
    float o = b2[n];
    for (int k = 0; k < H1N; k++) o = fmaf(fmaxf(acc[k], 0.0f), W2[n * H1N + k], o);
    return o;
}

// ---------------------------------------------------------------------------
// Precompute: grid (48, 2). Block (n, chunk) samples 257 grid points and emits
// 256 buckets as (m, c): f(x) ~ m*x + c on the bucket.
// ---------------------------------------------------------------------------
__global__ __launch_bounds__(256) void gam_precompute_kernel(
    const float* __restrict__ W0, const float* __restrict__ b0,
    const float* __restrict__ W1, const float* __restrict__ b1,
    const float* __restrict__ W2, const float* __restrict__ b2)
{
    __shared__ float sw0[H0N], sb0[H0N];
    __shared__ float sW1[H0N * H1N];
    __shared__ float sb1[H1N], sw2[H1N];
    __shared__ float sb2;
    __shared__ float yv[257];

    const int n  = blockIdx.x;
    const int p0 = blockIdx.y * 256;
    const int t  = threadIdx.x;

    for (int i = t; i < H0N * H1N; i += 256) sW1[i] = W1[n * H0N * H1N + i];
    if (t < H0N) {
        sw0[t] = W0[n * H0N + t];
        sb0[t] = b0[n * H0N + t];
    }
    if (t >= 64 && t < 64 + H1N) sb1[t - 64] = b1[n * H1N + (t - 64)];
    if (t >= 96 && t < 96 + H1N) sw2[t - 96] = W2[n * H1N + (t - 96)];
    if (t == 128) sb2 = b2[n];
    __syncthreads();

    for (int i = t; i < 257; i += 256) {
        const float x = fmaf((float)(p0 + i), WB, XMIN);   // exact grid point
        float acc[H1N];
        #pragma unroll
        for (int k = 0; k < H1N; k++) acc[k] = sb1[k];
        #pragma unroll 4
        for (int j = 0; j < H0N; j++) {
            const float h0 = fmaxf(fmaf(x, sw0[j], sb0[j]), 0.0f);
            const float* w1r = &sW1[j * H1N];
            #pragma unroll
            for (int k = 0; k < H1N; k++) acc[k] = fmaf(w1r[k], h0, acc[k]);
        }
        float o = sb2;
        #pragma unroll
        for (int k = 0; k < H1N; k++) o = fmaf(fmaxf(acc[k], 0.0f), sw2[k], o);
        yv[i] = o;
    }
    __syncthreads();

    {
        const int b = p0 + t;
        const float m  = (yv[t + 1] - yv[t]) * INVW;
        const float xL = fmaf((float)b, WB, XMIN);
        const float c  = fmaf(-m, xL, yv[t]);
        g_tab[n][b] = make_float2(m, c);
    }
}

// ---------------------------------------------------------------------------
// Eval: 296 blocks x 1024 threads (2 per SM).
// Warp = 16 duos (d = tid&15) x 2 rows (rrel = tid>>4 in 0..63).
// A block (bid<148): duo d<12 -> cols 2d..2d+1 (num feats 2d,2d+1);
//                    d>=12   -> cols 48+2(d-12).. (cat feats 2(d-12),..).
// B block: num feats 24..47 and cat feats 8..15, cols shifted accordingly.
// Gather: one LDS.64 at qbase[b*2+f]; r = fma(m, x, c).
// ---------------------------------------------------------------------------
struct QCtx {
    const float2* qbase;
    float scale, off, bound;
    int nbm1, fbase;
};

__device__ __forceinline__ float2 eval_duo(
    const QCtx& ctx, const float2 v,
    const float* __restrict__ W0, const float* __restrict__ b0,
    const float* __restrict__ W1, const float* __restrict__ b1,
    const float* __restrict__ W2, const float* __restrict__ b2)
{
    const float xs[2] = {v.x, v.y};
    float os[2];
    bool bad = false;
    #pragma unroll
    for (int f = 0; f < 2; f++) {
        const float x = xs[f];
        int b = (int)fmaf(x, ctx.scale, ctx.off);
        b = min(max(b, 0), ctx.nbm1);
        const float2 mc = ctx.qbase[b * 2 + f];
        os[f] = fmaf(mc.x, x, mc.y);
        bad |= (fabsf(x) > ctx.bound);
    }
    if (__builtin_expect(bad, 0)) {   // numeric |x|>6: ~never
        #pragma unroll
        for (int f = 0; f < 2; f++)
            if (fabsf(xs[f]) > ctx.bound)
                os[f] = mlp_exact(ctx.fbase + f, xs[f], W0, b0, W1, b1, W2, b2);
    }
    return make_float2(os[0], os[1]);
}

__global__ __launch_bounds__(EVAL_TPB, 2) void gam_eval_kernel(
    const float* __restrict__ in,
    const float* __restrict__ cb,
    const float* __restrict__ W0, const float* __restrict__ b0,
    const float* __restrict__ W1, const float* __restrict__ b1,
    const float* __restrict__ W2, const float* __restrict__ b2,
    float* __restrict__ out)
{
    extern __shared__ float2 sTab[];

    const int bid    = blockIdx.x;
    const bool typeA = (bid < NSLOT);
    const int slot   = typeA ? bid : bid - NSLOT;
    const int tid    = threadIdx.x;
    const int nbase  = typeA ? 0 : 24;    // first numeric feature of this block
    const int cbase  = typeA ? 0 : 8;     // first cat feature of this block

    // ---- stage tables: 24 numeric features -> 12 duo regions ----
    for (int i = tid; i < 24 * NB; i += EVAL_TPB) {
        const int n = i >> 9;             // 0..23
        const int b = i & (NB - 1);
        sTab[(n >> 1) * REG_F2 + b * 2 + (n & 1)] = g_tab[nbase + n][b];
    }
    // 8 cat features -> 4 duo regions (m=0, c=bias)
    for (int i = tid; i < 8 * 32; i += EVAL_TPB) {
        const int c = i >> 5;             // 0..7
        const int x = i & 31;
        sTab[CATOFF_F2 + (c >> 1) * CAT_F2 + x * 2 + (c & 1)] =
            make_float2(0.0f, cb[(cbase + c) * 32 + x]);
    }
    __syncthreads();

    const int d    = tid & 15;            // duo 0..15
    const int rrel = tid >> 4;            // 0..63
    const bool isnum = (d < 12);

    // global column of this duo
    const int col = isnum ? ((typeA ? 0 : 24) + 2 * d)
                          : (48 + 2 * (cbase / 2) * 1 + 2 * (d - 12) + (typeA ? 0 : 16));
    // (A: 48 + 2(d-12); B: 56 + 2(d-12) + ... simplify below)

    const int colq = isnum ? ((typeA ? 0 : 24) + 2 * d)
                           : ((typeA ? 48 : 56) + 2 * (d - 12));

    QCtx ctx;
    ctx.qbase = isnum ? (sTab + d * REG_F2)
                      : (sTab + CATOFF_F2 + (d - 12) * CAT_F2);
    ctx.scale = isnum ? SCALE : 1.0f;
    ctx.off   = isnum ? OFFB  : 0.0f;
    ctx.bound = isnum ? XMAX  : 1e30f;
    ctx.nbm1  = isnum ? (NB - 1) : 31;
    ctx.fbase = (typeA ? 0 : 24) + 2 * d;   // only used on numeric fallback

    (void)col;

    const int start = slot * ROWS_PB;
    const int rend  = min(start + ROWS_PB, BSZ);

    int r0 = start;
    for (; r0 + 128 <= rend; r0 += 128) {
        const int rowa = r0 + rrel;
        const int rowb = rowa + 64;
        const float2 va = *reinterpret_cast<const float2*>(in + rowa * NCOL + colq);
        const float2 vb = *reinterpret_cast<const float2*>(in + rowb * NCOL + colq);
        const float2 oa = eval_duo(ctx, va, W0, b0, W1, b1, W2, b2);
        *reinterpret_cast<float2*>(out + rowa * NCOL + colq) = oa;
        const float2 ob = eval_duo(ctx, vb, W0, b0, W1, b1, W2, b2);
        *reinterpret_cast<float2*>(out + rowb * NCOL + colq) = ob;
    }
    for (; r0 < rend; r0 += 64) {
        const int row = r0 + rrel;
        if (row < rend) {
            const float2 v = *reinterpret_cast<const float2*>(in + row * NCOL + colq);
            const float2 o = eval_duo(ctx, v, W0, b0, W1, b1, W2, b2);
            *reinterpret_cast<float2*>(out + row * NCOL + colq) = o;
        }
    }
}

extern "C" void kernel_launch(void* const* d_in, const int* in_sizes, int n_in,
                              void* d_out, int out_size)
{
    const float* in = (const float*)d_in[0];
    const float* W0 = (const float*)d_in[1];
    const float* b0 = (const float*)d_in[2];
    const float* W1 = (const float*)d_in[3];
    const float* b1 = (const float*)d_in[4];
    const float* W2 = (const float*)d_in[5];
    const float* b2 = (const float*)d_in[6];
    const float* cb = (const float*)d_in[7];
    float* out = (float*)d_out;

    static bool attr_done = false;
    if (!attr_done) {
        cudaFuncSetAttribute(gam_eval_kernel,
                             cudaFuncAttributeMaxDynamicSharedMemorySize,
                             (int)SMEM_EVAL);
        attr_done = true;
    }

    gam_precompute_kernel<<<dim3(NF, 2, 1), 256>>>(W0, b0, W1, b1, W2, b2);

    gam_eval_kernel<<<EVAL_GRID, EVAL_TPB, SMEM_EVAL>>>(
        in, cb, W0, b0, W1, b1, W2, b2, out);
}

// round 13
// speedup vs baseline: 2.0763x; 2.0763x over previous
#include <cuda_runtime.h>
#include <math.h>

// pyGAMNet on GB300.
// Cols 0..47: per-feature scalar MLP 1->40->20->1 (ReLU)  == scalar function f_n(x).
// Cols 48..63: class_bias[c, (int)x] gather.
//
// R13 = R8 (best verified: 23.04us) with ONE change: precompute emits the
// chord tables already in the eval kernel's interleaved smem layout
// [region][b*4+f], so eval staging is a contiguous conflict-free copy
// instead of stride-4 scattered STS. Eval loop is bit-identical to R8.

#define BSZ   131072
#define NCOL  64
#define NF    48
#define H0N   40
#define H1N   20

#define NB    512
#define XMIN  (-6.0f)
#define XMAX  (6.0f)
#define WB    (12.0f / 512.0f)        // 3/128, exact in fp32
#define SCALE (512.0f / 12.0f)
#define INVW  (512.0f / 12.0f)

#define EVAL_TPB   1024
#define EVAL_GRID  148
#define ROWS_PB    ((BSZ + EVAL_GRID - 1) / EVAL_GRID)   // 886

// smem: 12 numeric regions of (NB*4+1) float2, then 4 cat regions of (32*4+1)
#define REG_F2     (NB * 4 + 1)                   // 2049
#define CAT_REG    (32 * 4 + 1)                   // 129
#define CAT_OFF    (12 * REG_F2)                  // 24588
#define TAB_F2     (CAT_OFF + 4 * CAT_REG)        // 25104
#define SMEM_EVAL  (TAB_F2 * 8)                   // 200832 B

// global tables in the SAME interleaved layout the eval smem uses:
// g_tabi[r * 4*NB + b*4 + f]  where r = n>>2, f = n&3
__device__ float2 g_tabi[12 * 4 * NB];

// ---------------------------------------------------------------------------
// Exact fallback: full MLP eval for one (feature, x). ~Never executed.
// ---------------------------------------------------------------------------
__device__ __noinline__ float mlp_exact(
    int n, float x,
    const float* __restrict__ W0, const float* __restrict__ b0,
    const float* __restrict__ W1, const float* __restrict__ b1,
    const float* __restrict__ W2, const float* __restrict__ b2)
{
    float acc[H1N];
    for (int k = 0; k < H1N; k++) acc[k] = b1[n * H1N + k];
    for (int j = 0; j < H0N; j++) {
        const float h0 = fmaxf(fmaf(x, W0[n * H0N + j], b0[n * H0N + j]), 0.0f);
        const float* w1r = &W1[(n * H0N + j) * H1N];
        for (int k = 0; k < H1N; k++) acc[k] = fmaf(w1r[k], h0, acc[k]);
    }
    float o = b2[n];
    for (int k = 0; k < H1N; k++) o = fmaf(fmaxf(acc[k], 0.0f), W2[n * H1N + k], o);
    return o;
}

// ---------------------------------------------------------------------------
// Precompute: grid (48, 2). Block (n, chunk) samples 257 grid points and emits
// 256 buckets as (m, c) lines, written directly in interleaved layout.
// ---------------------------------------------------------------------------
__global__ __launch_bounds__(256) void gam_precompute_kernel(
    const float* __restrict__ W0, const float* __restrict__ b0,
    const float* __restrict__ W1, const float* __restrict__ b1,
    const float* __restrict__ W2, const float* __restrict__ b2)
{
    __shared__ float sw0[H0N], sb0[H0N];
    __shared__ float sW1[H0N * H1N];
    __shared__ float sb1[H1N], sw2[H1N];
    __shared__ float sb2;
    __shared__ float yv[257];

    const int n  = blockIdx.x;
    const int p0 = blockIdx.y * 256;
    const int t  = threadIdx.x;

    for (int i = t; i < H0N * H1N; i += 256) sW1[i] = W1[n * H0N * H1N + i];
    if (t < H0N) {
        sw0[t] = W0[n * H0N + t];
        sb0[t] = b0[n * H0N + t];
    }
    if (t >= 64 && t < 64 + H1N) sb1[t - 64] = b1[n * H1N + (t - 64)];
    if (t >= 96 && t < 96 + H1N) sw2[t - 96] = W2[n * H1N + (t - 96)];
    if (t == 128) sb2 = b2[n];
    __syncthreads();

    for (int i = t; i < 257; i += 256) {
        const float x = fmaf((float)(p0 + i), WB, XMIN);   // exact grid point
        float acc[H1N];
        #pragma unroll
        for (int k = 0; k < H1N; k++) acc[k] = sb1[k];
        #pragma unroll 4
        for (int j = 0; j < H0N; j++) {
            const float h0 = fmaxf(fmaf(x, sw0[j], sb0[j]), 0.0f);
            const float* w1r = &sW1[j * H1N];
            #pragma unroll
            for (int k = 0; k < H1N; k++) acc[k] = fmaf(w1r[k], h0, acc[k]);
        }
        float o = sb2;
        #pragma unroll
        for (int k = 0; k < H1N; k++) o = fmaf(fmaxf(acc[k], 0.0f), sw2[k], o);
        yv[i] = o;
    }
    __syncthreads();

    {
        const int b = p0 + t;
        const float m  = (yv[t + 1] - yv[t]) * INVW;
        const float xL = fmaf((float)b, WB, XMIN);
        const float c  = fmaf(-m, xL, yv[t]);
        g_tabi[(n >> 2) * (4 * NB) + b * 4 + (n & 3)] = make_float2(m, c);
    }
}

// ---------------------------------------------------------------------------
// Eval: 148 persistent blocks x 1024 threads (identical to R8's loop).
// Thread -> (row = r0 + tid/16, quad q = tid%16): handles cols 4q..4q+3.
// ---------------------------------------------------------------------------
struct QCtx {
    const float2* qbase;
    float scale, off, bound;
    int nbm1, q;
};

__device__ __forceinline__ void eval_quad(
    const QCtx& ctx, const float4 v, float4& o,
    const float* __restrict__ W0, const float* __restrict__ b0,
    const float* __restrict__ W1, const float* __restrict__ b1,
    const float* __restrict__ W2, const float* __restrict__ b2)
{
    const float xs[4] = {v.x, v.y, v.z, v.w};
    float os[4];
    bool bad = false;
    #pragma unroll
    for (int f = 0; f < 4; f++) {
        const float x = xs[f];
        int b = (int)fmaf(x, ctx.scale, ctx.off);
        b = min(max(b, 0), ctx.nbm1);
        const float2 mc = ctx.qbase[b * 4 + f];
        os[f] = fmaf(mc.x, x, mc.y);
        bad |= (fabsf(x) > ctx.bound);
    }
    if (__builtin_expect(bad, 0)) {   // numeric |x|>6: ~never
        #pragma unroll
        for (int f = 0; f < 4; f++)
            if (fabsf(xs[f]) > ctx.bound)
                os[f] = mlp_exact(ctx.q * 4 + f, xs[f], W0, b0, W1, b1, W2, b2);
    }
    o = make_float4(os[0], os[1], os[2], os[3]);
}

__global__ __launch_bounds__(EVAL_TPB, 1) void gam_eval_kernel(
    const float* __restrict__ in,
    const float* __restrict__ cb,
    const float* __restrict__ W0, const float* __restrict__ b0,
    const float* __restrict__ W1, const float* __restrict__ b1,
    const float* __restrict__ W2, const float* __restrict__ b2,
    float* __restrict__ out)
{
    extern __shared__ float smem[];
    float2* sTab = (float2*)smem;     // [TAB_F2]

    const int tid = threadIdx.x;

    // numeric tables: contiguous copy per region (coalesced, conflict-free)
    #pragma unroll
    for (int r = 0; r < 12; r++) {
        const float2* src = g_tabi + r * (4 * NB);
        float2* dst = sTab + r * REG_F2;
        dst[tid]        = src[tid];
        dst[tid + 1024] = src[tid + 1024];
    }
    // cat tables: cb[c*32+x] -> (m=0, c=bias) in region 12+(c>>2)  (tiny)
    for (int i = tid; i < 16 * 32; i += EVAL_TPB) {
        const int c = i >> 5;
        const int x = i & 31;
        sTab[CAT_OFF + (c >> 2) * CAT_REG + x * 4 + (c & 3)] =
            make_float2(0.0f, cb[i]);
    }
    __syncthreads();

    const int start = blockIdx.x * ROWS_PB;
    const int rend  = min(start + ROWS_PB, BSZ);

    const int q    = tid & 15;
    const int rrel = tid >> 4;
    const bool isnum = (q < 12);

    QCtx ctx;
    ctx.q     = q;
    ctx.qbase = isnum ? (sTab + q * REG_F2)
                      : (sTab + CAT_OFF + (q - 12) * CAT_REG);
    ctx.scale = isnum ? SCALE : 1.0f;
    ctx.off   = isnum ? 256.0f : 0.0f;     // 6 * 512/12 = 256 exact
    ctx.bound = isnum ? XMAX : 1e30f;
    ctx.nbm1  = isnum ? (NB - 1) : 31;

    int r0 = start;
    #pragma unroll 2
    for (; r0 + 64 <= rend; r0 += 64) {
        const int row = r0 + rrel;
        const float4 v = *reinterpret_cast<const float4*>(in + row * NCOL + q * 4);
        float4 o;
        eval_quad(ctx, v, o, W0, b0, W1, b1, W2, b2);
        *reinterpret_cast<float4*>(out + row * NCOL + q * 4) = o;
    }
    {   // tail (< 64 rows)
        const int row = r0 + rrel;
        if (row < rend) {
            const float4 v = *reinterpret_cast<const float4*>(in + row * NCOL + q * 4);
            float4 o;
            eval_quad(ctx, v, o, W0, b0, W1, b1, W2, b2);
            *reinterpret_cast<float4*>(out + row * NCOL + q * 4) = o;
        }
    }
}

extern "C" void kernel_launch(void* const* d_in, const int* in_sizes, int n_in,
                              void* d_out, int out_size)
{
    const float* in = (const float*)d_in[0];
    const float* W0 = (const float*)d_in[1];
    const float* b0 = (const float*)d_in[2];
    const float* W1 = (const float*)d_in[3];
    const float* b1 = (const float*)d_in[4];
    const float* W2 = (const float*)d_in[5];
    const float* b2 = (const float*)d_in[6];
    const float* cb = (const float*)d_in[7];
    float* out = (float*)d_out;

    static bool attr_done = false;
    if (!attr_done) {
        cudaFuncSetAttribute(gam_eval_kernel,
                             cudaFuncAttributeMaxDynamicSharedMemorySize,
                             (int)SMEM_EVAL);
        attr_done = true;
    }

    gam_precompute_kernel<<<dim3(NF, 2, 1), 256>>>(W0, b0, W1, b1, W2, b2);

    gam_eval_kernel<<<EVAL_GRID, EVAL_TPB, SMEM_EVAL>>>(
        in, cb, W0, b0, W1, b1, W2, b2, out);
}